// round 1
// baseline (speedup 1.0000x reference)
#include <cuda_runtime.h>
#include <math.h>

// Problem constants
#define T_TOK  8192      // 4 * 2048 tokens
#define DM     1024      // d_model
#define NE     8         // experts
#define FH     4096      // ffn hidden
#define NPAIR  (T_TOK*2) // (token, k) pairs; every token has exactly 2

// ---------------- scratch (device globals; no allocation allowed) ----------
__device__ int   g_counts[NE];
__device__ int   g_pairs[NE][T_TOK];          // pair id = t*2+k, per-expert bucket
__device__ float g_cw[NPAIR];                 // combine weight per pair
__device__ float g_hidden[(size_t)NPAIR * FH]; // 256 MB: gelu(x@W1+b1) per pair
__device__ float g_y[(size_t)NPAIR * DM];      // 64 MB: (hidden@W2+b2) per pair

// ---------------- init ------------------------------------------------------
__global__ void zero_counts_kernel() {
    if (threadIdx.x < NE) g_counts[threadIdx.x] = 0;
}

// ---------------- gating: 1 warp per token ---------------------------------
__global__ __launch_bounds__(256) void gate_kernel(const float* __restrict__ x,
                                                   const float* __restrict__ wg) {
    const int t = blockIdx.x * 8 + (threadIdx.x >> 5);
    const int lane = threadIdx.x & 31;
    if (t >= T_TOK) return;
    const float* xr = x + (size_t)t * DM;

    float acc[NE];
    #pragma unroll
    for (int e = 0; e < NE; e++) acc[e] = 0.f;
    for (int d = lane; d < DM; d += 32) {
        const float xv = xr[d];
        #pragma unroll
        for (int e = 0; e < NE; e++) acc[e] += xv * wg[e * DM + d];
    }
    #pragma unroll
    for (int e = 0; e < NE; e++)
        #pragma unroll
        for (int o = 16; o > 0; o >>= 1)
            acc[e] += __shfl_xor_sync(0xffffffffu, acc[e], o);

    if (lane == 0) {
        // softmax over 8 logits
        float m = acc[0];
        #pragma unroll
        for (int e = 1; e < NE; e++) m = fmaxf(m, acc[e]);
        float p[NE], s = 0.f;
        #pragma unroll
        for (int e = 0; e < NE; e++) { p[e] = expf(acc[e] - m); s += p[e]; }
        const float inv = 1.f / s;
        #pragma unroll
        for (int e = 0; e < NE; e++) p[e] *= inv;
        // top-2, jax tie-break: lowest index first (strict >)
        int e0 = 0;
        #pragma unroll
        for (int e = 1; e < NE; e++) if (p[e] > p[e0]) e0 = e;
        int e1 = -1;
        #pragma unroll
        for (int e = 0; e < NE; e++) {
            if (e == e0) continue;
            if (e1 < 0 || p[e] > p[e1]) e1 = e;
        }
        const int ee[2] = { e0, e1 };
        #pragma unroll
        for (int k = 0; k < 2; k++) {
            const int e = ee[k];
            const int idx = atomicAdd(&g_counts[e], 1);
            g_pairs[e][idx] = t * 2 + k;
            g_cw[t * 2 + k] = p[e];
        }
    }
}

// ---------------- GEMM1: hidden[pair] = gelu(x[tok] @ W1[e] + b1[e]) -------
// 128x128 tile, TK=16, 256 threads, 8x8 per thread (split 4+4 halves).
__global__ __launch_bounds__(256) void gemm1_kernel(const float* __restrict__ x,
                                                    const float* __restrict__ W1,
                                                    const float* __restrict__ b1) {
    const int e = blockIdx.z;
    const int cnt = g_counts[e];
    const int row0 = blockIdx.y * 128;
    if (row0 >= cnt) return;
    const int n0 = blockIdx.x * 128;
    const float* __restrict__ Be  = W1 + (size_t)e * DM * FH;
    const float* __restrict__ b1e = b1 + (size_t)e * FH;

    __shared__ float As[16][128];
    __shared__ float Bs[16][128];
    __shared__ int   s_pair[128];

    const int tid = threadIdx.x;
    if (tid < 128) {
        const int slot = row0 + tid;
        s_pair[tid] = (slot < cnt) ? g_pairs[e][slot] : -1;
    }
    __syncthreads();

    const int tx = tid & 15, ty = tid >> 4;

    // A-load mapping: thread owns row mA, 8 consecutive k at offset koff
    const int mA   = tid >> 1;
    const int koff = (tid & 1) * 8;
    const int pmA  = s_pair[mA];
    const float* aptr = (pmA >= 0) ? (x + (size_t)(pmA >> 1) * DM + koff) : nullptr;

    // B-load mapping: thread owns k-row kB, 8 consecutive n at offset nB
    const int kB = tid >> 4;
    const int nB = (tid & 15) * 8;
    const float* bptr = Be + (size_t)kB * FH + n0 + nB;

    float acc[8][8];
    #pragma unroll
    for (int i = 0; i < 8; i++)
        #pragma unroll
        for (int j = 0; j < 8; j++) acc[i][j] = 0.f;

    for (int k0 = 0; k0 < DM; k0 += 16) {
        float4 a0 = make_float4(0.f,0.f,0.f,0.f), a1 = a0;
        if (aptr) {
            a0 = *(const float4*)(aptr + k0);
            a1 = *(const float4*)(aptr + k0 + 4);
        }
        const float4 bv0 = *(const float4*)(bptr + (size_t)k0 * FH);
        const float4 bv1 = *(const float4*)(bptr + (size_t)k0 * FH + 4);
        __syncthreads();
        As[koff+0][mA] = a0.x; As[koff+1][mA] = a0.y;
        As[koff+2][mA] = a0.z; As[koff+3][mA] = a0.w;
        As[koff+4][mA] = a1.x; As[koff+5][mA] = a1.y;
        As[koff+6][mA] = a1.z; As[koff+7][mA] = a1.w;
        *(float4*)&Bs[kB][nB]     = bv0;
        *(float4*)&Bs[kB][nB + 4] = bv1;
        __syncthreads();
        #pragma unroll
        for (int k = 0; k < 16; k++) {
            const float4 av0 = *(const float4*)&As[k][ty*4];
            const float4 av1 = *(const float4*)&As[k][64 + ty*4];
            const float4 cv0 = *(const float4*)&Bs[k][tx*4];
            const float4 cv1 = *(const float4*)&Bs[k][64 + tx*4];
            const float a[8] = {av0.x,av0.y,av0.z,av0.w, av1.x,av1.y,av1.z,av1.w};
            const float b[8] = {cv0.x,cv0.y,cv0.z,cv0.w, cv1.x,cv1.y,cv1.z,cv1.w};
            #pragma unroll
            for (int i = 0; i < 8; i++)
                #pragma unroll
                for (int j = 0; j < 8; j++) acc[i][j] += a[i] * b[j];
        }
    }

    #pragma unroll
    for (int i = 0; i < 8; i++) {
        const int m = (i < 4) ? (ty*4 + i) : (64 + ty*4 + (i - 4));
        const int pm = s_pair[m];
        if (pm < 0) continue;
        float* dst = g_hidden + (size_t)pm * FH + n0;
        #pragma unroll
        for (int half = 0; half < 2; half++) {
            const int cbase = half ? (64 + tx*4) : (tx*4);
            float4 v;
            float* vv = &v.x;
            #pragma unroll
            for (int j = 0; j < 4; j++) {
                const float tt = acc[i][half*4 + j] + b1e[n0 + cbase + j];
                vv[j] = 0.5f * tt * (1.0f + erff(tt * 0.70710678118654752f));
            }
            *(float4*)(dst + cbase) = v;
        }
    }
}

// ---------------- GEMM2: y[pair] = hidden[pair] @ W2[e] + b2[e] ------------
__global__ __launch_bounds__(256) void gemm2_kernel(const float* __restrict__ W2,
                                                    const float* __restrict__ b2) {
    const int e = blockIdx.z;
    const int cnt = g_counts[e];
    const int row0 = blockIdx.y * 128;
    if (row0 >= cnt) return;
    const int n0 = blockIdx.x * 128;
    const float* __restrict__ Be  = W2 + (size_t)e * FH * DM;
    const float* __restrict__ b2e = b2 + (size_t)e * DM;

    __shared__ float As[16][128];
    __shared__ float Bs[16][128];
    __shared__ int   s_pair[128];

    const int tid = threadIdx.x;
    if (tid < 128) {
        const int slot = row0 + tid;
        s_pair[tid] = (slot < cnt) ? g_pairs[e][slot] : -1;
    }
    __syncthreads();

    const int tx = tid & 15, ty = tid >> 4;

    const int mA   = tid >> 1;
    const int koff = (tid & 1) * 8;
    const int pmA  = s_pair[mA];
    const float* aptr = (pmA >= 0) ? (g_hidden + (size_t)pmA * FH + koff) : nullptr;

    const int kB = tid >> 4;
    const int nB = (tid & 15) * 8;
    const float* bptr = Be + (size_t)kB * DM + n0 + nB;

    float acc[8][8];
    #pragma unroll
    for (int i = 0; i < 8; i++)
        #pragma unroll
        for (int j = 0; j < 8; j++) acc[i][j] = 0.f;

    for (int k0 = 0; k0 < FH; k0 += 16) {
        float4 a0 = make_float4(0.f,0.f,0.f,0.f), a1 = a0;
        if (aptr) {
            a0 = *(const float4*)(aptr + k0);
            a1 = *(const float4*)(aptr + k0 + 4);
        }
        const float4 bv0 = *(const float4*)(bptr + (size_t)k0 * DM);
        const float4 bv1 = *(const float4*)(bptr + (size_t)k0 * DM + 4);
        __syncthreads();
        As[koff+0][mA] = a0.x; As[koff+1][mA] = a0.y;
        As[koff+2][mA] = a0.z; As[koff+3][mA] = a0.w;
        As[koff+4][mA] = a1.x; As[koff+5][mA] = a1.y;
        As[koff+6][mA] = a1.z; As[koff+7][mA] = a1.w;
        *(float4*)&Bs[kB][nB]     = bv0;
        *(float4*)&Bs[kB][nB + 4] = bv1;
        __syncthreads();
        #pragma unroll
        for (int k = 0; k < 16; k++) {
            const float4 av0 = *(const float4*)&As[k][ty*4];
            const float4 av1 = *(const float4*)&As[k][64 + ty*4];
            const float4 cv0 = *(const float4*)&Bs[k][tx*4];
            const float4 cv1 = *(const float4*)&Bs[k][64 + tx*4];
            const float a[8] = {av0.x,av0.y,av0.z,av0.w, av1.x,av1.y,av1.z,av1.w};
            const float b[8] = {cv0.x,cv0.y,cv0.z,cv0.w, cv1.x,cv1.y,cv1.z,cv1.w};
            #pragma unroll
            for (int i = 0; i < 8; i++)
                #pragma unroll
                for (int j = 0; j < 8; j++) acc[i][j] += a[i] * b[j];
        }
    }

    #pragma unroll
    for (int i = 0; i < 8; i++) {
        const int m = (i < 4) ? (ty*4 + i) : (64 + ty*4 + (i - 4));
        const int pm = s_pair[m];
        if (pm < 0) continue;
        float* dst = g_y + (size_t)pm * DM + n0;
        #pragma unroll
        for (int half = 0; half < 2; half++) {
            const int cbase = half ? (64 + tx*4) : (tx*4);
            float4 v;
            float* vv = &v.x;
            #pragma unroll
            for (int j = 0; j < 4; j++)
                vv[j] = acc[i][half*4 + j] + b2e[n0 + cbase + j];
            *(float4*)(dst + cbase) = v;
        }
    }
}

// ---------------- combine: out[t] = cw0*y[2t] + cw1*y[2t+1] ----------------
__global__ __launch_bounds__(256) void combine_kernel(float* __restrict__ out) {
    const int per_tok = DM / 4;
    const int i = blockIdx.x * blockDim.x + threadIdx.x;
    if (i >= T_TOK * per_tok) return;
    const int t = i / per_tok;
    const int c = i - t * per_tok;
    const float w0 = g_cw[2*t], w1 = g_cw[2*t + 1];
    const float4* y = (const float4*)g_y;
    const float4 a = y[(size_t)(2*t)     * per_tok + c];
    const float4 b = y[(size_t)(2*t + 1) * per_tok + c];
    float4 r;
    r.x = w0*a.x + w1*b.x;
    r.y = w0*a.y + w1*b.y;
    r.z = w0*a.z + w1*b.z;
    r.w = w0*a.w + w1*b.w;
    ((float4*)out)[i] = r;
}

// ---------------- launch ----------------------------------------------------
extern "C" void kernel_launch(void* const* d_in, const int* in_sizes, int n_in,
                              void* d_out, int out_size) {
    const float* x  = (const float*)d_in[0];
    const float* wg = (const float*)d_in[1];
    const float* W1 = (const float*)d_in[2];
    const float* b1 = (const float*)d_in[3];
    const float* W2 = (const float*)d_in[4];
    const float* b2 = (const float*)d_in[5];
    float* out = (float*)d_out;

    zero_counts_kernel<<<1, 32>>>();
    gate_kernel<<<T_TOK / 8, 256>>>(x, wg);
    gemm1_kernel<<<dim3(FH / 128, T_TOK / 128, NE), 256>>>(x, W1, b1);
    gemm2_kernel<<<dim3(DM / 128, T_TOK / 128, NE), 256>>>(W2, b2);
    combine_kernel<<<(T_TOK * (DM / 4) + 255) / 256, 256>>>(out);
}

// round 8
// speedup vs baseline: 1.8181x; 1.8181x over previous
#include <cuda_runtime.h>
#include <cuda_bf16.h>
#include <math.h>
#include <stdint.h>

#define T_TOK  8192
#define DM     1024
#define NE     8
#define FH     4096
#define NPAIR  (T_TOK*2)

// smem: 2 stages x 16KB. Stage: Ah[128m x 32B] Al Bh[16k x 256B] Bl (4KB each)
#define STAGE_B    16384
#define SMEM_TOTAL 32768

// ---------------- scratch (device globals; ~320MB total, R1-proven scale) ---
__device__ int   g_counts[NE];
__device__ int   g_off[NE];
__device__ int   g_pairs[NE][T_TOK];
__device__ float g_cw[NPAIR];
__device__ __align__(256) __nv_bfloat16 g_hh[(size_t)NPAIR * FH];  // hidden hi
__device__ __align__(256) __nv_bfloat16 g_hl[(size_t)NPAIR * FH];  // hidden lo
__device__ __align__(256) float g_y[(size_t)NPAIR * DM];

// ---------------- helpers ----------------------------------------------------
__device__ __forceinline__ uint32_t smem_u32(const void* p) {
    return (uint32_t)__cvta_generic_to_shared(p);
}
__device__ __forceinline__ void ldsm4(uint32_t* r, uint32_t addr) {
    asm volatile("ldmatrix.sync.aligned.m8n8.x4.shared.b16 {%0,%1,%2,%3}, [%4];"
                 : "=r"(r[0]), "=r"(r[1]), "=r"(r[2]), "=r"(r[3]) : "r"(addr));
}
__device__ __forceinline__ void ldsm4_t(uint32_t* r, uint32_t addr) {
    asm volatile("ldmatrix.sync.aligned.m8n8.x4.trans.shared.b16 {%0,%1,%2,%3}, [%4];"
                 : "=r"(r[0]), "=r"(r[1]), "=r"(r[2]), "=r"(r[3]) : "r"(addr));
}
__device__ __forceinline__ void mma_bf16(float* c, const uint32_t* a, const uint32_t* b) {
    asm volatile("mma.sync.aligned.m16n8k16.row.col.f32.bf16.bf16.f32 "
                 "{%0,%1,%2,%3}, {%4,%5,%6,%7}, {%8,%9}, {%0,%1,%2,%3};"
                 : "+f"(c[0]), "+f"(c[1]), "+f"(c[2]), "+f"(c[3])
                 : "r"(a[0]), "r"(a[1]), "r"(a[2]), "r"(a[3]), "r"(b[0]), "r"(b[1]));
}
// split 8 fp32 -> packed bf16 hi/lo (8 each)
__device__ __forceinline__ void split8(const float* v, uint4& h4, uint4& l4) {
    uint32_t h[4], l[4];
    #pragma unroll
    for (int j = 0; j < 4; j++) {
        __nv_bfloat16 h0 = __float2bfloat16(v[2*j]);
        __nv_bfloat16 h1 = __float2bfloat16(v[2*j+1]);
        float r0 = v[2*j]   - __bfloat162float(h0);
        float r1 = v[2*j+1] - __bfloat162float(h1);
        __nv_bfloat16 q0 = __float2bfloat16(r0), q1 = __float2bfloat16(r1);
        h[j] = (uint32_t)__bfloat16_as_ushort(h0) | ((uint32_t)__bfloat16_as_ushort(h1) << 16);
        l[j] = (uint32_t)__bfloat16_as_ushort(q0) | ((uint32_t)__bfloat16_as_ushort(q1) << 16);
    }
    h4 = make_uint4(h[0], h[1], h[2], h[3]);
    l4 = make_uint4(l[0], l[1], l[2], l[3]);
}

// ---------------- small kernels ---------------------------------------------
__global__ void zero_counts_kernel() {
    if (threadIdx.x < NE) g_counts[threadIdx.x] = 0;
}
__global__ void prefix_kernel() {
    if (threadIdx.x == 0) {
        int s = 0;
        for (int e = 0; e < NE; e++) { g_off[e] = s; s += g_counts[e]; }
    }
}

__global__ __launch_bounds__(256) void gate_kernel(const float* __restrict__ x,
                                                   const float* __restrict__ wg) {
    const int t = blockIdx.x * 8 + (threadIdx.x >> 5);
    const int lane = threadIdx.x & 31;
    if (t >= T_TOK) return;
    const float* xr = x + (size_t)t * DM;
    float acc[NE];
    #pragma unroll
    for (int e = 0; e < NE; e++) acc[e] = 0.f;
    for (int d = lane; d < DM; d += 32) {
        const float xv = xr[d];
        #pragma unroll
        for (int e = 0; e < NE; e++) acc[e] += xv * wg[e * DM + d];
    }
    #pragma unroll
    for (int e = 0; e < NE; e++)
        #pragma unroll
        for (int o = 16; o > 0; o >>= 1)
            acc[e] += __shfl_xor_sync(0xffffffffu, acc[e], o);
    if (lane == 0) {
        float m = acc[0];
        #pragma unroll
        for (int e = 1; e < NE; e++) m = fmaxf(m, acc[e]);
        float p[NE], s = 0.f;
        #pragma unroll
        for (int e = 0; e < NE; e++) { p[e] = expf(acc[e] - m); s += p[e]; }
        const float inv = 1.f / s;
        #pragma unroll
        for (int e = 0; e < NE; e++) p[e] *= inv;
        int e0 = 0;
        #pragma unroll
        for (int e = 1; e < NE; e++) if (p[e] > p[e0]) e0 = e;
        int e1 = -1;
        #pragma unroll
        for (int e = 0; e < NE; e++) {
            if (e == e0) continue;
            if (e1 < 0 || p[e] > p[e1]) e1 = e;
        }
        const int ee[2] = { e0, e1 };
        #pragma unroll
        for (int k = 0; k < 2; k++) {
            const int e = ee[k];
            const int idx = atomicAdd(&g_counts[e], 1);
            g_pairs[e][idx] = t * 2 + k;
            g_cw[t * 2 + k] = p[e];
        }
    }
}

// ---------------- unified mma mainloop ---------------------------------------
// CTA 128x128, 8 warps (2x4), warp tile 64x32, K chunks of 16.
// A smem: [m][k] 32B rows, XOR-swizzled 16B halves; read w/ ldmatrix (non-trans).
// B smem: [k][n] 256B rows, XOR-swizzled 16B chunks; read w/ ldmatrix.trans.
// Weights arrive fp32 (global), split hi/lo in registers.
// Compensated bf16: acc += ah*bh + ah*bl + al*bh.
template<int KTOT, int BSTRIDE, bool SPLIT_A>
__device__ __forceinline__ void gemm_mainloop(
    const float* __restrict__ xsrc, const int* s_tok,         // SPLIT_A path
    const __nv_bfloat16* __restrict__ Ahg,
    const __nv_bfloat16* __restrict__ Alg, size_t a_row0,     // !SPLIT_A path
    const float* __restrict__ Bsrc, int n0,
    char* smem, float (&acc)[4][4][4])
{
    const int NCH = KTOT / 16;
    const int tid = threadIdx.x;
    const uint32_t sbase = smem_u32(smem);

    // loader mapping
    const int am = tid >> 1, ahalf = tid & 1;          // A: row, 8-k half
    const int bk = tid >> 4, bn = tid & 15;            // B: k-row, 8-n chunk
    const uint32_t aoff = (uint32_t)(am * 32 + ((ahalf ^ ((am >> 2) & 1)) * 16));
    const uint32_t boff = (uint32_t)(bk * 256 + ((bn ^ (bk & 7)) * 16));

    const float* axp = nullptr;
    const __nv_bfloat16 *ahp = nullptr, *alp = nullptr;
    if constexpr (SPLIT_A) {
        axp = xsrc + (size_t)s_tok[am] * DM + ahalf * 8;
    } else {
        size_t r = a_row0 + am;
        if (r > (size_t)(NPAIR - 1)) r = NPAIR - 1;
        ahp = Ahg + r * KTOT + ahalf * 8;
        alp = Alg + r * KTOT + ahalf * 8;
    }
    const float* bbase = Bsrc + (size_t)bk * BSTRIDE + n0 + bn * 8;

    // fragment geometry
    const int lane = tid & 31, wid = tid >> 5;
    const int wm = (wid >> 2) * 64, wn = (wid & 3) * 32;
    const int rA = wm + (lane & 15);
    const uint32_t offA = (uint32_t)(rA * 32) +
                          ((((lane >> 4) & 1) ^ ((rA >> 2) & 1)) ? 16u : 0u);
    const int bkr = lane & 15;                     // B ldsm k-row
    const int bnc0 = (wn >> 3) + ((lane >> 4) & 1); // B ldsm n-chunk base

    float ax[8]; uint4 ahv, alv; float bx[8];

    #define LDG_CHUNK(c_) do {                                                   \
        const int kb = (c_) * 16;                                                \
        if constexpr (SPLIT_A) {                                                 \
            float4 t0 = *(const float4*)(axp + kb);                              \
            float4 t1 = *(const float4*)(axp + kb + 4);                          \
            ax[0]=t0.x; ax[1]=t0.y; ax[2]=t0.z; ax[3]=t0.w;                      \
            ax[4]=t1.x; ax[5]=t1.y; ax[6]=t1.z; ax[7]=t1.w;                      \
        } else {                                                                 \
            ahv = *(const uint4*)(ahp + kb);                                     \
            alv = *(const uint4*)(alp + kb);                                     \
        }                                                                        \
        const float* bp = bbase + (size_t)kb * BSTRIDE;                          \
        float4 u0 = *(const float4*)(bp);                                        \
        float4 u1 = *(const float4*)(bp + 4);                                    \
        bx[0]=u0.x; bx[1]=u0.y; bx[2]=u0.z; bx[3]=u0.w;                          \
        bx[4]=u1.x; bx[5]=u1.y; bx[6]=u1.z; bx[7]=u1.w;                          \
    } while (0)

    #define STS_CHUNK(s_) do {                                                   \
        char* st = smem + (s_) * STAGE_B;                                        \
        if constexpr (SPLIT_A) {                                                 \
            uint4 h4, l4; split8(ax, h4, l4);                                    \
            *(uint4*)(st + aoff)        = h4;                                    \
            *(uint4*)(st + 4096 + aoff) = l4;                                    \
        } else {                                                                 \
            *(uint4*)(st + aoff)        = ahv;                                   \
            *(uint4*)(st + 4096 + aoff) = alv;                                   \
        }                                                                        \
        uint4 bh4, bl4; split8(bx, bh4, bl4);                                    \
        *(uint4*)(st + 8192  + boff) = bh4;                                      \
        *(uint4*)(st + 12288 + boff) = bl4;                                      \
    } while (0)

    LDG_CHUNK(0);
    for (int c = 0; c < NCH; c++) {
        const int s = c & 1;
        __syncthreads();            // prior reads of stage s (iter c-2) are done
        STS_CHUNK(s);
        if (c + 1 < NCH) LDG_CHUNK(c + 1);
        __syncthreads();            // stage s stores visible
        const uint32_t so = sbase + (uint32_t)s * STAGE_B;

        uint32_t ah[4][4], al[4][4], bh[2][4], bl[2][4];
        #pragma unroll
        for (int i = 0; i < 4; i++) {
            ldsm4(ah[i], so + offA + (uint32_t)(i * 16 * 32));
            ldsm4(al[i], so + 4096u + offA + (uint32_t)(i * 16 * 32));
        }
        #pragma unroll
        for (int jp = 0; jp < 2; jp++) {
            const uint32_t bo = (uint32_t)(bkr * 256 +
                                (((bnc0 + jp * 2) ^ (bkr & 7)) * 16));
            ldsm4_t(bh[jp], so + 8192u  + bo);
            ldsm4_t(bl[jp], so + 12288u + bo);
        }
        #pragma unroll
        for (int i = 0; i < 4; i++)
            #pragma unroll
            for (int j = 0; j < 4; j++) {
                const uint32_t* ph = &bh[j >> 1][(j & 1) * 2];
                const uint32_t* pl = &bl[j >> 1][(j & 1) * 2];
                mma_bf16(acc[i][j], ah[i], ph);
                mma_bf16(acc[i][j], ah[i], pl);
                mma_bf16(acc[i][j], al[i], ph);
            }
    }
    #undef LDG_CHUNK
    #undef STS_CHUNK
}

// ---------------- GEMM1: hidden = gelu(x @ W1 + b1) -> bf16 hi/lo -----------
__global__ __launch_bounds__(256)
void gemm1_kernel(const float* __restrict__ x, const float* __restrict__ W1,
                  const float* __restrict__ b1) {
    const int e = blockIdx.z;
    const int cnt = g_counts[e];
    const int row0 = blockIdx.y * 128;
    if (row0 >= cnt) return;
    const int n0 = blockIdx.x * 128;

    __shared__ __align__(128) char smem_buf[SMEM_TOTAL];
    __shared__ int s_tok[128];
    const int tid = threadIdx.x;
    if (tid < 128) {
        const int slot = row0 + tid;
        s_tok[tid] = (slot < cnt) ? (g_pairs[e][slot] >> 1) : 0;
    }
    __syncthreads();
    const int off_e = g_off[e];

    float acc[4][4][4];
    #pragma unroll
    for (int i = 0; i < 4; i++)
        #pragma unroll
        for (int j = 0; j < 4; j++)
            #pragma unroll
            for (int q = 0; q < 4; q++) acc[i][j][q] = 0.f;

    gemm_mainloop<DM, FH, true>(x, s_tok, nullptr, nullptr, 0,
                                W1 + (size_t)e * DM * FH, n0, smem_buf, acc);

    const int lane = tid & 31, wid = tid >> 5;
    const int wm = (wid >> 2) * 64, wn = (wid & 3) * 32;
    const float* b1e = b1 + (size_t)e * FH + n0;
    const int rem = cnt - row0;

    #pragma unroll
    for (int i = 0; i < 4; i++) {
        #pragma unroll
        for (int j = 0; j < 4; j++) {
            const int col = wn + j * 8 + 2 * (lane & 3);
            const float bb0 = b1e[col], bb1 = b1e[col + 1];
            #pragma unroll
            for (int h = 0; h < 2; h++) {
                const int r = wm + i * 16 + (lane >> 2) + h * 8;
                if (r < rem) {
                    const size_t slot = (size_t)off_e + row0 + r;
                    const float t0 = acc[i][j][2*h]   + bb0;
                    const float t1 = acc[i][j][2*h+1] + bb1;
                    const float q0 = 0.5f * t0 * (1.0f + erff(t0 * 0.70710678118654752440f));
                    const float q1 = 0.5f * t1 * (1.0f + erff(t1 * 0.70710678118654752440f));
                    __nv_bfloat16 h0 = __float2bfloat16(q0), h1 = __float2bfloat16(q1);
                    const float l0 = q0 - __bfloat162float(h0);
                    const float l1 = q1 - __bfloat162float(h1);
                    __nv_bfloat16 o0 = __float2bfloat16(l0), o1 = __float2bfloat16(l1);
                    const uint32_t vh = (uint32_t)__bfloat16_as_ushort(h0) |
                                        ((uint32_t)__bfloat16_as_ushort(h1) << 16);
                    const uint32_t vl = (uint32_t)__bfloat16_as_ushort(o0) |
                                        ((uint32_t)__bfloat16_as_ushort(o1) << 16);
                    *(uint32_t*)(g_hh + slot * FH + n0 + col) = vh;
                    *(uint32_t*)(g_hl + slot * FH + n0 + col) = vl;
                }
            }
        }
    }
}

// ---------------- GEMM2: y = hidden @ W2 + b2 -------------------------------
__global__ __launch_bounds__(256)
void gemm2_kernel(const float* __restrict__ W2, const float* __restrict__ b2) {
    const int e = blockIdx.z;
    const int cnt = g_counts[e];
    const int row0 = blockIdx.y * 128;
    if (row0 >= cnt) return;
    const int n0 = blockIdx.x * 128;

    __shared__ __align__(128) char smem_buf[SMEM_TOTAL];
    const int tid = threadIdx.x;
    const int off_e = g_off[e];

    float acc[4][4][4];
    #pragma unroll
    for (int i = 0; i < 4; i++)
        #pragma unroll
        for (int j = 0; j < 4; j++)
            #pragma unroll
            for (int q = 0; q < 4; q++) acc[i][j][q] = 0.f;

    gemm_mainloop<FH, DM, false>(nullptr, nullptr, g_hh, g_hl,
                                 (size_t)(off_e + row0),
                                 W2 + (size_t)e * FH * DM, n0, smem_buf, acc);

    const int lane = tid & 31, wid = tid >> 5;
    const int wm = (wid >> 2) * 64, wn = (wid & 3) * 32;
    const float* b2e = b2 + (size_t)e * DM + n0;

    #pragma unroll
    for (int i = 0; i < 4; i++) {
        #pragma unroll
        for (int j = 0; j < 4; j++) {
            const int col = wn + j * 8 + 2 * (lane & 3);
            const float bb0 = b2e[col], bb1 = b2e[col + 1];
            #pragma unroll
            for (int h = 0; h < 2; h++) {
                const int r = wm + i * 16 + (lane >> 2) + h * 8;
                if (row0 + r < cnt) {
                    const int pair = g_pairs[e][row0 + r];
                    float2 v;
                    v.x = acc[i][j][2*h]   + bb0;
                    v.y = acc[i][j][2*h+1] + bb1;
                    *(float2*)(g_y + (size_t)pair * DM + n0 + col) = v;
                }
            }
        }
    }
}

// ---------------- combine ----------------------------------------------------
__global__ __launch_bounds__(256) void combine_kernel(float* __restrict__ out) {
    const int per_tok = DM / 4;
    const int i = blockIdx.x * blockDim.x + threadIdx.x;
    if (i >= T_TOK * per_tok) return;
    const int t = i / per_tok;
    const int c = i - t * per_tok;
    const float w0 = g_cw[2*t], w1 = g_cw[2*t + 1];
    const float4* y = (const float4*)g_y;
    const float4 a = y[(size_t)(2*t)     * per_tok + c];
    const float4 b = y[(size_t)(2*t + 1) * per_tok + c];
    float4 r;
    r.x = w0*a.x + w1*b.x;
    r.y = w0*a.y + w1*b.y;
    r.z = w0*a.z + w1*b.z;
    r.w = w0*a.w + w1*b.w;
    ((float4*)out)[i] = r;
}

// ---------------- launch ----------------------------------------------------
extern "C" void kernel_launch(void* const* d_in, const int* in_sizes, int n_in,
                              void* d_out, int out_size) {
    const float* x  = (const float*)d_in[0];
    const float* wg = (const float*)d_in[1];
    const float* W1 = (const float*)d_in[2];
    const float* b1 = (const float*)d_in[3];
    const float* W2 = (const float*)d_in[4];
    const float* b2 = (const float*)d_in[5];
    float* out = (float*)d_out;

    zero_counts_kernel<<<1, 32>>>();
    gate_kernel<<<T_TOK / 8, 256>>>(x, wg);
    prefix_kernel<<<1, 1>>>();
    gemm1_kernel<<<dim3(FH / 128, T_TOK / 128, NE), 256>>>(x, W1, b1);
    gemm2_kernel<<<dim3(DM / 128, T_TOK / 128, NE), 256>>>(W2, b2);
    combine_kernel<<<(T_TOK * (DM / 4) + 255) / 256, 256>>>(out);
}

// round 9
// speedup vs baseline: 2.2576x; 1.2417x over previous
#include <cuda_runtime.h>
#include <cuda_bf16.h>
#include <math.h>
#include <stdint.h>

#define T_TOK  8192
#define DM     1024
#define NE     8
#define FH     4096
#define NPAIR  (T_TOK*2)

// smem: 2 stages x 16KB. Stage: Ah[128m x 32B] Al Bh[16k x 256B] Bl (4KB each)
#define STAGE_B    16384
#define SMEM_TOTAL 32768

// ---------------- scratch (device globals; ~320MB total, R1-proven scale) ---
__device__ int   g_counts[NE];
__device__ int   g_off[NE];
__device__ int   g_pairs[NE][T_TOK];
__device__ float g_cw[NPAIR];
__device__ __align__(256) __nv_bfloat16 g_hh[(size_t)NPAIR * FH];  // hidden hi
__device__ __align__(256) __nv_bfloat16 g_hl[(size_t)NPAIR * FH];  // hidden lo
__device__ __align__(256) float g_y[(size_t)NPAIR * DM];

// ---------------- helpers ----------------------------------------------------
__device__ __forceinline__ uint32_t smem_u32(const void* p) {
    return (uint32_t)__cvta_generic_to_shared(p);
}
__device__ __forceinline__ void ldsm4(uint32_t* r, uint32_t addr) {
    asm volatile("ldmatrix.sync.aligned.m8n8.x4.shared.b16 {%0,%1,%2,%3}, [%4];"
                 : "=r"(r[0]), "=r"(r[1]), "=r"(r[2]), "=r"(r[3]) : "r"(addr));
}
__device__ __forceinline__ void ldsm4_t(uint32_t* r, uint32_t addr) {
    asm volatile("ldmatrix.sync.aligned.m8n8.x4.trans.shared.b16 {%0,%1,%2,%3}, [%4];"
                 : "=r"(r[0]), "=r"(r[1]), "=r"(r[2]), "=r"(r[3]) : "r"(addr));
}
__device__ __forceinline__ void mma_bf16(float* c, const uint32_t* a, const uint32_t* b) {
    asm volatile("mma.sync.aligned.m16n8k16.row.col.f32.bf16.bf16.f32 "
                 "{%0,%1,%2,%3}, {%4,%5,%6,%7}, {%8,%9}, {%0,%1,%2,%3};"
                 : "+f"(c[0]), "+f"(c[1]), "+f"(c[2]), "+f"(c[3])
                 : "r"(a[0]), "r"(a[1]), "r"(a[2]), "r"(a[3]), "r"(b[0]), "r"(b[1]));
}
// split 8 fp32 -> packed bf16 hi/lo (8 each)
__device__ __forceinline__ void split8(const float* v, uint4& h4, uint4& l4) {
    uint32_t h[4], l[4];
    #pragma unroll
    for (int j = 0; j < 4; j++) {
        __nv_bfloat16 h0 = __float2bfloat16(v[2*j]);
        __nv_bfloat16 h1 = __float2bfloat16(v[2*j+1]);
        float r0 = v[2*j]   - __bfloat162float(h0);
        float r1 = v[2*j+1] - __bfloat162float(h1);
        __nv_bfloat16 q0 = __float2bfloat16(r0), q1 = __float2bfloat16(r1);
        h[j] = (uint32_t)__bfloat16_as_ushort(h0) | ((uint32_t)__bfloat16_as_ushort(h1) << 16);
        l[j] = (uint32_t)__bfloat16_as_ushort(q0) | ((uint32_t)__bfloat16_as_ushort(q1) << 16);
    }
    h4 = make_uint4(h[0], h[1], h[2], h[3]);
    l4 = make_uint4(l[0], l[1], l[2], l[3]);
}

// ---------------- small kernels ---------------------------------------------
__global__ void zero_counts_kernel() {
    if (threadIdx.x < NE) g_counts[threadIdx.x] = 0;
}
__global__ void prefix_kernel() {
    if (threadIdx.x == 0) {
        int s = 0;
        for (int e = 0; e < NE; e++) { g_off[e] = s; s += g_counts[e]; }
    }
}

__global__ __launch_bounds__(256) void gate_kernel(const float* __restrict__ x,
                                                   const float* __restrict__ wg) {
    const int t = blockIdx.x * 8 + (threadIdx.x >> 5);
    const int lane = threadIdx.x & 31;
    if (t >= T_TOK) return;
    const float* xr = x + (size_t)t * DM;
    float acc[NE];
    #pragma unroll
    for (int e = 0; e < NE; e++) acc[e] = 0.f;
    for (int d = lane; d < DM; d += 32) {
        const float xv = xr[d];
        #pragma unroll
        for (int e = 0; e < NE; e++) acc[e] += xv * wg[e * DM + d];
    }
    #pragma unroll
    for (int e = 0; e < NE; e++)
        #pragma unroll
        for (int o = 16; o > 0; o >>= 1)
            acc[e] += __shfl_xor_sync(0xffffffffu, acc[e], o);
    if (lane == 0) {
        float m = acc[0];
        #pragma unroll
        for (int e = 1; e < NE; e++) m = fmaxf(m, acc[e]);
        float p[NE], s = 0.f;
        #pragma unroll
        for (int e = 0; e < NE; e++) { p[e] = expf(acc[e] - m); s += p[e]; }
        const float inv = 1.f / s;
        #pragma unroll
        for (int e = 0; e < NE; e++) p[e] *= inv;
        int e0 = 0;
        #pragma unroll
        for (int e = 1; e < NE; e++) if (p[e] > p[e0]) e0 = e;
        int e1 = -1;
        #pragma unroll
        for (int e = 0; e < NE; e++) {
            if (e == e0) continue;
            if (e1 < 0 || p[e] > p[e1]) e1 = e;
        }
        const int ee[2] = { e0, e1 };
        #pragma unroll
        for (int k = 0; k < 2; k++) {
            const int e = ee[k];
            const int idx = atomicAdd(&g_counts[e], 1);
            g_pairs[e][idx] = t * 2 + k;
            g_cw[t * 2 + k] = p[e];
        }
    }
}

// ---------------- unified mma mainloop ---------------------------------------
// CTA 128x128, 8 warps (2x4), warp tile 64x32, K chunks of 16.
// A smem: [m][k] 32B rows, XOR-swizzled 16B halves; read w/ ldmatrix (non-trans).
// B smem: [k][n] 256B rows, XOR-swizzled 16B chunks; read w/ ldmatrix.trans.
// Weights arrive fp32 (global), split hi/lo in registers.
// Compensated bf16: acc += ah*bh + ah*bl + al*bh.
template<int KTOT, int BSTRIDE, bool SPLIT_A>
__device__ __forceinline__ void gemm_mainloop(
    const float* __restrict__ xsrc, const int* s_tok,         // SPLIT_A path
    const __nv_bfloat16* __restrict__ Ahg,
    const __nv_bfloat16* __restrict__ Alg, size_t a_row0,     // !SPLIT_A path
    const float* __restrict__ Bsrc, int n0,
    char* smem, float (&acc)[4][4][4])
{
    const int NCH = KTOT / 16;
    const int tid = threadIdx.x;
    const uint32_t sbase = smem_u32(smem);

    // loader mapping
    const int am = tid >> 1, ahalf = tid & 1;          // A: row, 8-k half
    const int bk = tid >> 4, bn = tid & 15;            // B: k-row, 8-n chunk
    const uint32_t aoff = (uint32_t)(am * 32 + ((ahalf ^ ((am >> 2) & 1)) * 16));
    const uint32_t boff = (uint32_t)(bk * 256 + ((bn ^ (bk & 7)) * 16));

    const float* axp = nullptr;
    const __nv_bfloat16 *ahp = nullptr, *alp = nullptr;
    if constexpr (SPLIT_A) {
        axp = xsrc + (size_t)s_tok[am] * DM + ahalf * 8;
    } else {
        size_t r = a_row0 + am;
        if (r > (size_t)(NPAIR - 1)) r = NPAIR - 1;
        ahp = Ahg + r * KTOT + ahalf * 8;
        alp = Alg + r * KTOT + ahalf * 8;
    }
    const float* bbase = Bsrc + (size_t)bk * BSTRIDE + n0 + bn * 8;

    // fragment geometry
    const int lane = tid & 31, wid = tid >> 5;
    const int wm = (wid >> 2) * 64, wn = (wid & 3) * 32;
    const int rA = wm + (lane & 15);
    const uint32_t offA = (uint32_t)(rA * 32) +
                          ((((lane >> 4) & 1) ^ ((rA >> 2) & 1)) ? 16u : 0u);
    const int bkr = lane & 15;                     // B ldsm k-row
    const int bnc0 = (wn >> 3) + ((lane >> 4) & 1); // B ldsm n-chunk base

    float ax[8]; uint4 ahv, alv; float bx[8];

    #define LDG_CHUNK(c_) do {                                                   \
        const int kb = (c_) * 16;                                                \
        if constexpr (SPLIT_A) {                                                 \
            float4 t0 = *(const float4*)(axp + kb);                              \
            float4 t1 = *(const float4*)(axp + kb + 4);                          \
            ax[0]=t0.x; ax[1]=t0.y; ax[2]=t0.z; ax[3]=t0.w;                      \
            ax[4]=t1.x; ax[5]=t1.y; ax[6]=t1.z; ax[7]=t1.w;                      \
        } else {                                                                 \
            ahv = *(const uint4*)(ahp + kb);                                     \
            alv = *(const uint4*)(alp + kb);                                     \
        }                                                                        \
        const float* bp = bbase + (size_t)kb * BSTRIDE;                          \
        float4 u0 = *(const float4*)(bp);                                        \
        float4 u1 = *(const float4*)(bp + 4);                                    \
        bx[0]=u0.x; bx[1]=u0.y; bx[2]=u0.z; bx[3]=u0.w;                          \
        bx[4]=u1.x; bx[5]=u1.y; bx[6]=u1.z; bx[7]=u1.w;                          \
    } while (0)

    #define STS_CHUNK(s_) do {                                                   \
        char* st = smem + (s_) * STAGE_B;                                        \
        if constexpr (SPLIT_A) {                                                 \
            uint4 h4, l4; split8(ax, h4, l4);                                    \
            *(uint4*)(st + aoff)        = h4;                                    \
            *(uint4*)(st + 4096 + aoff) = l4;                                    \
        } else {                                                                 \
            *(uint4*)(st + aoff)        = ahv;                                   \
            *(uint4*)(st + 4096 + aoff) = alv;                                   \
        }                                                                        \
        uint4 bh4, bl4; split8(bx, bh4, bl4);                                    \
        *(uint4*)(st + 8192  + boff) = bh4;                                      \
        *(uint4*)(st + 12288 + boff) = bl4;                                      \
    } while (0)

    LDG_CHUNK(0);
    for (int c = 0; c < NCH; c++) {
        const int s = c & 1;
        __syncthreads();            // prior reads of stage s (iter c-2) are done
        STS_CHUNK(s);
        if (c + 1 < NCH) LDG_CHUNK(c + 1);
        __syncthreads();            // stage s stores visible
        const uint32_t so = sbase + (uint32_t)s * STAGE_B;

        uint32_t ah[4][4], al[4][4], bh[2][4], bl[2][4];
        #pragma unroll
        for (int i = 0; i < 4; i++) {
            ldsm4(ah[i], so + offA + (uint32_t)(i * 16 * 32));
            ldsm4(al[i], so + 4096u + offA + (uint32_t)(i * 16 * 32));
        }
        #pragma unroll
        for (int jp = 0; jp < 2; jp++) {
            const uint32_t bo = (uint32_t)(bkr * 256 +
                                (((bnc0 + jp * 2) ^ (bkr & 7)) * 16));
            ldsm4_t(bh[jp], so + 8192u  + bo);
            ldsm4_t(bl[jp], so + 12288u + bo);
        }
        #pragma unroll
        for (int i = 0; i < 4; i++)
            #pragma unroll
            for (int j = 0; j < 4; j++) {
                const uint32_t* ph = &bh[j >> 1][(j & 1) * 2];
                const uint32_t* pl = &bl[j >> 1][(j & 1) * 2];
                mma_bf16(acc[i][j], ah[i], ph);
                mma_bf16(acc[i][j], ah[i], pl);
                mma_bf16(acc[i][j], al[i], ph);
            }
    }
    #undef LDG_CHUNK
    #undef STS_CHUNK
}

// ---------------- GEMM1: hidden = gelu(x @ W1 + b1) -> bf16 hi/lo -----------
__global__ __launch_bounds__(256, 2)
void gemm1_kernel(const float* __restrict__ x, const float* __restrict__ W1,
                  const float* __restrict__ b1) {
    const int e = blockIdx.z;
    const int cnt = g_counts[e];
    const int row0 = blockIdx.y * 128;
    if (row0 >= cnt) return;
    const int n0 = blockIdx.x * 128;

    __shared__ __align__(128) char smem_buf[SMEM_TOTAL];
    __shared__ int s_tok[128];
    const int tid = threadIdx.x;
    if (tid < 128) {
        const int slot = row0 + tid;
        s_tok[tid] = (slot < cnt) ? (g_pairs[e][slot] >> 1) : 0;
    }
    __syncthreads();
    const int off_e = g_off[e];

    float acc[4][4][4];
    #pragma unroll
    for (int i = 0; i < 4; i++)
        #pragma unroll
        for (int j = 0; j < 4; j++)
            #pragma unroll
            for (int q = 0; q < 4; q++) acc[i][j][q] = 0.f;

    gemm_mainloop<DM, FH, true>(x, s_tok, nullptr, nullptr, 0,
                                W1 + (size_t)e * DM * FH, n0, smem_buf, acc);

    const int lane = tid & 31, wid = tid >> 5;
    const int wm = (wid >> 2) * 64, wn = (wid & 3) * 32;
    const float* b1e = b1 + (size_t)e * FH + n0;
    const int rem = cnt - row0;

    #pragma unroll
    for (int i = 0; i < 4; i++) {
        #pragma unroll
        for (int j = 0; j < 4; j++) {
            const int col = wn + j * 8 + 2 * (lane & 3);
            const float bb0 = b1e[col], bb1 = b1e[col + 1];
            #pragma unroll
            for (int h = 0; h < 2; h++) {
                const int r = wm + i * 16 + (lane >> 2) + h * 8;
                if (r < rem) {
                    const size_t slot = (size_t)off_e + row0 + r;
                    const float t0 = acc[i][j][2*h]   + bb0;
                    const float t1 = acc[i][j][2*h+1] + bb1;
                    const float q0 = 0.5f * t0 * (1.0f + erff(t0 * 0.70710678118654752440f));
                    const float q1 = 0.5f * t1 * (1.0f + erff(t1 * 0.70710678118654752440f));
                    __nv_bfloat16 h0 = __float2bfloat16(q0), h1 = __float2bfloat16(q1);
                    const float l0 = q0 - __bfloat162float(h0);
                    const float l1 = q1 - __bfloat162float(h1);
                    __nv_bfloat16 o0 = __float2bfloat16(l0), o1 = __float2bfloat16(l1);
                    const uint32_t vh = (uint32_t)__bfloat16_as_ushort(h0) |
                                        ((uint32_t)__bfloat16_as_ushort(h1) << 16);
                    const uint32_t vl = (uint32_t)__bfloat16_as_ushort(o0) |
                                        ((uint32_t)__bfloat16_as_ushort(o1) << 16);
                    *(uint32_t*)(g_hh + slot * FH + n0 + col) = vh;
                    *(uint32_t*)(g_hl + slot * FH + n0 + col) = vl;
                }
            }
        }
    }
}

// ---------------- GEMM2: y = hidden @ W2 + b2 -------------------------------
__global__ __launch_bounds__(256, 2)
void gemm2_kernel(const float* __restrict__ W2, const float* __restrict__ b2) {
    const int e = blockIdx.z;
    const int cnt = g_counts[e];
    const int row0 = blockIdx.y * 128;
    if (row0 >= cnt) return;
    const int n0 = blockIdx.x * 128;

    __shared__ __align__(128) char smem_buf[SMEM_TOTAL];
    const int tid = threadIdx.x;
    const int off_e = g_off[e];

    float acc[4][4][4];
    #pragma unroll
    for (int i = 0; i < 4; i++)
        #pragma unroll
        for (int j = 0; j < 4; j++)
            #pragma unroll
            for (int q = 0; q < 4; q++) acc[i][j][q] = 0.f;

    gemm_mainloop<FH, DM, false>(nullptr, nullptr, g_hh, g_hl,
                                 (size_t)(off_e + row0),
                                 W2 + (size_t)e * FH * DM, n0, smem_buf, acc);

    const int lane = tid & 31, wid = tid >> 5;
    const int wm = (wid >> 2) * 64, wn = (wid & 3) * 32;
    const float* b2e = b2 + (size_t)e * DM + n0;

    #pragma unroll
    for (int i = 0; i < 4; i++) {
        #pragma unroll
        for (int j = 0; j < 4; j++) {
            const int col = wn + j * 8 + 2 * (lane & 3);
            const float bb0 = b2e[col], bb1 = b2e[col + 1];
            #pragma unroll
            for (int h = 0; h < 2; h++) {
                const int r = wm + i * 16 + (lane >> 2) + h * 8;
                if (row0 + r < cnt) {
                    const int pair = g_pairs[e][row0 + r];
                    float2 v;
                    v.x = acc[i][j][2*h]   + bb0;
                    v.y = acc[i][j][2*h+1] + bb1;
                    *(float2*)(g_y + (size_t)pair * DM + n0 + col) = v;
                }
            }
        }
    }
}

// ---------------- combine ----------------------------------------------------
__global__ __launch_bounds__(256) void combine_kernel(float* __restrict__ out) {
    const int per_tok = DM / 4;
    const int i = blockIdx.x * blockDim.x + threadIdx.x;
    if (i >= T_TOK * per_tok) return;
    const int t = i / per_tok;
    const int c = i - t * per_tok;
    const float w0 = g_cw[2*t], w1 = g_cw[2*t + 1];
    const float4* y = (const float4*)g_y;
    const float4 a = y[(size_t)(2*t)     * per_tok + c];
    const float4 b = y[(size_t)(2*t + 1) * per_tok + c];
    float4 r;
    r.x = w0*a.x + w1*b.x;
    r.y = w0*a.y + w1*b.y;
    r.z = w0*a.z + w1*b.z;
    r.w = w0*a.w + w1*b.w;
    ((float4*)out)[i] = r;
}

// ---------------- launch ----------------------------------------------------
extern "C" void kernel_launch(void* const* d_in, const int* in_sizes, int n_in,
                              void* d_out, int out_size) {
    const float* x  = (const float*)d_in[0];
    const float* wg = (const float*)d_in[1];
    const float* W1 = (const float*)d_in[2];
    const float* b1 = (const float*)d_in[3];
    const float* W2 = (const float*)d_in[4];
    const float* b2 = (const float*)d_in[5];
    float* out = (float*)d_out;

    zero_counts_kernel<<<1, 32>>>();
    gate_kernel<<<T_TOK / 8, 256>>>(x, wg);
    prefix_kernel<<<1, 1>>>();
    gemm1_kernel<<<dim3(FH / 128, T_TOK / 128, NE), 256>>>(x, W1, b1);
    gemm2_kernel<<<dim3(DM / 128, T_TOK / 128, NE), 256>>>(W2, b2);
    combine_kernel<<<(T_TOK * (DM / 4) + 255) / 256, 256>>>(out);
}

// round 10
// speedup vs baseline: 2.4892x; 1.1026x over previous
#include <cuda_runtime.h>
#include <cuda_bf16.h>
#include <math.h>
#include <stdint.h>

#define T_TOK  8192
#define DM     1024
#define NE     8
#define FH     4096
#define NPAIR  (T_TOK*2)

// smem: 2 stages x 16KB. Stage: Ah[128m x 32B] Al Bh[16k x 256B] Bl (4KB each)
#define STAGE_B    16384
#define SMEM_TOTAL 32768

// ---------------- scratch (device globals; ~320MB total) --------------------
__device__ int   g_counts[NE];
__device__ int   g_off[NE];
__device__ int   g_pairs[NE][T_TOK];
__device__ float g_cw[NPAIR];
__device__ __align__(256) __nv_bfloat16 g_hh[(size_t)NPAIR * FH];  // hidden hi
__device__ __align__(256) __nv_bfloat16 g_hl[(size_t)NPAIR * FH];  // hidden lo
__device__ __align__(256) float g_y[(size_t)NPAIR * DM];

// ---------------- helpers ----------------------------------------------------
__device__ __forceinline__ uint32_t smem_u32(const void* p) {
    return (uint32_t)__cvta_generic_to_shared(p);
}
__device__ __forceinline__ void ldsm4(uint32_t* r, uint32_t addr) {
    asm volatile("ldmatrix.sync.aligned.m8n8.x4.shared.b16 {%0,%1,%2,%3}, [%4];"
                 : "=r"(r[0]), "=r"(r[1]), "=r"(r[2]), "=r"(r[3]) : "r"(addr));
}
__device__ __forceinline__ void ldsm4_t(uint32_t* r, uint32_t addr) {
    asm volatile("ldmatrix.sync.aligned.m8n8.x4.trans.shared.b16 {%0,%1,%2,%3}, [%4];"
                 : "=r"(r[0]), "=r"(r[1]), "=r"(r[2]), "=r"(r[3]) : "r"(addr));
}
__device__ __forceinline__ void mma_bf16(float* c, const uint32_t* a, const uint32_t* b) {
    asm volatile("mma.sync.aligned.m16n8k16.row.col.f32.bf16.bf16.f32 "
                 "{%0,%1,%2,%3}, {%4,%5,%6,%7}, {%8,%9}, {%0,%1,%2,%3};"
                 : "+f"(c[0]), "+f"(c[1]), "+f"(c[2]), "+f"(c[3])
                 : "r"(a[0]), "r"(a[1]), "r"(a[2]), "r"(a[3]), "r"(b[0]), "r"(b[1]));
}
// split 8 fp32 -> packed bf16 hi/lo (8 each)
__device__ __forceinline__ void split8(const float* v, uint4& h4, uint4& l4) {
    uint32_t h[4], l[4];
    #pragma unroll
    for (int j = 0; j < 4; j++) {
        __nv_bfloat16 h0 = __float2bfloat16(v[2*j]);
        __nv_bfloat16 h1 = __float2bfloat16(v[2*j+1]);
        float r0 = v[2*j]   - __bfloat162float(h0);
        float r1 = v[2*j+1] - __bfloat162float(h1);
        __nv_bfloat16 q0 = __float2bfloat16(r0), q1 = __float2bfloat16(r1);
        h[j] = (uint32_t)__bfloat16_as_ushort(h0) | ((uint32_t)__bfloat16_as_ushort(h1) << 16);
        l[j] = (uint32_t)__bfloat16_as_ushort(q0) | ((uint32_t)__bfloat16_as_ushort(q1) << 16);
    }
    h4 = make_uint4(h[0], h[1], h[2], h[3]);
    l4 = make_uint4(l[0], l[1], l[2], l[3]);
}

// ---------------- small kernels ---------------------------------------------
__global__ void zero_counts_kernel() {
    if (threadIdx.x < NE) g_counts[threadIdx.x] = 0;
}
__global__ void prefix_kernel() {
    if (threadIdx.x == 0) {
        int s = 0;
        for (int e = 0; e < NE; e++) { g_off[e] = s; s += g_counts[e]; }
    }
}

__global__ __launch_bounds__(256) void gate_kernel(const float* __restrict__ x,
                                                   const float* __restrict__ wg) {
    const int t = blockIdx.x * 8 + (threadIdx.x >> 5);
    const int lane = threadIdx.x & 31;
    if (t >= T_TOK) return;
    const float* xr = x + (size_t)t * DM;
    float acc[NE];
    #pragma unroll
    for (int e = 0; e < NE; e++) acc[e] = 0.f;
    for (int d = lane; d < DM; d += 32) {
        const float xv = xr[d];
        #pragma unroll
        for (int e = 0; e < NE; e++) acc[e] += xv * wg[e * DM + d];
    }
    #pragma unroll
    for (int e = 0; e < NE; e++)
        #pragma unroll
        for (int o = 16; o > 0; o >>= 1)
            acc[e] += __shfl_xor_sync(0xffffffffu, acc[e], o);
    if (lane == 0) {
        float m = acc[0];
        #pragma unroll
        for (int e = 1; e < NE; e++) m = fmaxf(m, acc[e]);
        float p[NE], s = 0.f;
        #pragma unroll
        for (int e = 0; e < NE; e++) { p[e] = expf(acc[e] - m); s += p[e]; }
        const float inv = 1.f / s;
        #pragma unroll
        for (int e = 0; e < NE; e++) p[e] *= inv;
        int e0 = 0;
        #pragma unroll
        for (int e = 1; e < NE; e++) if (p[e] > p[e0]) e0 = e;
        int e1 = -1;
        #pragma unroll
        for (int e = 0; e < NE; e++) {
            if (e == e0) continue;
            if (e1 < 0 || p[e] > p[e1]) e1 = e;
        }
        const int ee[2] = { e0, e1 };
        #pragma unroll
        for (int k = 0; k < 2; k++) {
            const int e = ee[k];
            const int idx = atomicAdd(&g_counts[e], 1);
            g_pairs[e][idx] = t * 2 + k;
            g_cw[t * 2 + k] = p[e];
        }
    }
}

// ---------------- unified mma mainloop ---------------------------------------
// CTA 128x128, 8 warps (2x4), warp tile 64x32, K chunks of 16.
// A smem: [m][k] 32B rows, XOR-swizzled 16B halves; ldmatrix (non-trans).
// B smem: [k][n] 256B rows, XOR-swizzled 16B chunks; ldmatrix.trans.
// Double buffer, ONE sync per chunk (safe: a warp reaches STS(s)@c only after
// sync@c-1, which all warps pass only after their ldsm(s)@c-2 completed).
// Compensated bf16, term-major MMA order (16 independent MMAs per pass).
template<int KTOT, int BSTRIDE, bool SPLIT_A>
__device__ __forceinline__ void gemm_mainloop(
    const float* __restrict__ xsrc, const int* s_tok,         // SPLIT_A path
    const __nv_bfloat16* __restrict__ Ahg,
    const __nv_bfloat16* __restrict__ Alg, size_t a_row0,     // !SPLIT_A path
    const float* __restrict__ Bsrc, int n0,
    char* smem, float (&acc)[4][4][4])
{
    const int NCH = KTOT / 16;
    const int tid = threadIdx.x;
    const uint32_t sbase = smem_u32(smem);

    // loader mapping
    const int am = tid >> 1, ahalf = tid & 1;          // A: row, 8-k half
    const int bk = tid >> 4, bn = tid & 15;            // B: k-row, 8-n chunk
    const uint32_t aoff = (uint32_t)(am * 32 + ((ahalf ^ ((am >> 2) & 1)) * 16));
    const uint32_t boff = (uint32_t)(bk * 256 + ((bn ^ (bk & 7)) * 16));

    const float* axp = nullptr;
    const __nv_bfloat16 *ahp = nullptr, *alp = nullptr;
    if constexpr (SPLIT_A) {
        axp = xsrc + (size_t)s_tok[am] * DM + ahalf * 8;
    } else {
        size_t r = a_row0 + am;
        if (r > (size_t)(NPAIR - 1)) r = NPAIR - 1;
        ahp = Ahg + r * KTOT + ahalf * 8;
        alp = Alg + r * KTOT + ahalf * 8;
    }
    const float* bbase = Bsrc + (size_t)bk * BSTRIDE + n0 + bn * 8;

    // fragment geometry
    const int lane = tid & 31, wid = tid >> 5;
    const int wm = (wid >> 2) * 64, wn = (wid & 3) * 32;
    const int rA = wm + (lane & 15);
    const uint32_t offA = (uint32_t)(rA * 32) +
                          ((((lane >> 4) & 1) ^ ((rA >> 2) & 1)) ? 16u : 0u);
    const int bkr = lane & 15;                      // B ldsm k-row
    const int bnc0 = (wn >> 3) + ((lane >> 4) & 1); // B ldsm n-chunk base

    float ax[8]; uint4 ahv, alv; float bx[8];

    #define LDG_CHUNK(c_) do {                                                   \
        const int kb = (c_) * 16;                                                \
        if constexpr (SPLIT_A) {                                                 \
            float4 t0 = *(const float4*)(axp + kb);                              \
            float4 t1 = *(const float4*)(axp + kb + 4);                          \
            ax[0]=t0.x; ax[1]=t0.y; ax[2]=t0.z; ax[3]=t0.w;                      \
            ax[4]=t1.x; ax[5]=t1.y; ax[6]=t1.z; ax[7]=t1.w;                      \
        } else {                                                                 \
            ahv = *(const uint4*)(ahp + kb);                                     \
            alv = *(const uint4*)(alp + kb);                                     \
        }                                                                        \
        const float* bp = bbase + (size_t)kb * BSTRIDE;                          \
        float4 u0 = *(const float4*)(bp);                                        \
        float4 u1 = *(const float4*)(bp + 4);                                    \
        bx[0]=u0.x; bx[1]=u0.y; bx[2]=u0.z; bx[3]=u0.w;                          \
        bx[4]=u1.x; bx[5]=u1.y; bx[6]=u1.z; bx[7]=u1.w;                          \
    } while (0)

    #define STS_CHUNK(s_) do {                                                   \
        char* st = smem + (s_) * STAGE_B;                                        \
        if constexpr (SPLIT_A) {                                                 \
            uint4 h4, l4; split8(ax, h4, l4);                                    \
            *(uint4*)(st + aoff)        = h4;                                    \
            *(uint4*)(st + 4096 + aoff) = l4;                                    \
        } else {                                                                 \
            *(uint4*)(st + aoff)        = ahv;                                   \
            *(uint4*)(st + 4096 + aoff) = alv;                                   \
        }                                                                        \
        uint4 bh4, bl4; split8(bx, bh4, bl4);                                    \
        *(uint4*)(st + 8192  + boff) = bh4;                                      \
        *(uint4*)(st + 12288 + boff) = bl4;                                      \
    } while (0)

    LDG_CHUNK(0);
    for (int c = 0; c < NCH; c++) {
        const int s = c & 1;
        STS_CHUNK(s);
        if (c + 1 < NCH) LDG_CHUNK(c + 1);
        __syncthreads();            // stage s stores visible; c-2 reads done
        const uint32_t so = sbase + (uint32_t)s * STAGE_B;

        uint32_t ah[4][4], al[4][4], bh[2][4], bl[2][4];
        #pragma unroll
        for (int i = 0; i < 4; i++) {
            ldsm4(ah[i], so + offA + (uint32_t)(i * 16 * 32));
            ldsm4(al[i], so + 4096u + offA + (uint32_t)(i * 16 * 32));
        }
        #pragma unroll
        for (int jp = 0; jp < 2; jp++) {
            const uint32_t bo = (uint32_t)(bkr * 256 +
                                (((bnc0 + jp * 2) ^ (bkr & 7)) * 16));
            ldsm4_t(bh[jp], so + 8192u  + bo);
            ldsm4_t(bl[jp], so + 12288u + bo);
        }
        // term-major: three passes of 16 independent MMAs each
        #pragma unroll
        for (int i = 0; i < 4; i++)
            #pragma unroll
            for (int j = 0; j < 4; j++)
                mma_bf16(acc[i][j], ah[i], &bh[j >> 1][(j & 1) * 2]);
        #pragma unroll
        for (int i = 0; i < 4; i++)
            #pragma unroll
            for (int j = 0; j < 4; j++)
                mma_bf16(acc[i][j], ah[i], &bl[j >> 1][(j & 1) * 2]);
        #pragma unroll
        for (int i = 0; i < 4; i++)
            #pragma unroll
            for (int j = 0; j < 4; j++)
                mma_bf16(acc[i][j], al[i], &bh[j >> 1][(j & 1) * 2]);
    }
    #undef LDG_CHUNK
    #undef STS_CHUNK
}

// ---------------- GEMM1: hidden = gelu(x @ W1 + b1) -> bf16 hi/lo -----------
__global__ __launch_bounds__(256, 2)
void gemm1_kernel(const float* __restrict__ x, const float* __restrict__ W1,
                  const float* __restrict__ b1) {
    const int e = blockIdx.z;
    const int cnt = g_counts[e];
    const int row0 = blockIdx.y * 128;
    if (row0 >= cnt) return;
    const int n0 = blockIdx.x * 128;

    __shared__ __align__(128) char smem_buf[SMEM_TOTAL];
    __shared__ int s_tok[128];
    const int tid = threadIdx.x;
    if (tid < 128) {
        const int slot = row0 + tid;
        s_tok[tid] = (slot < cnt) ? (g_pairs[e][slot] >> 1) : 0;
    }
    __syncthreads();
    const int off_e = g_off[e];

    float acc[4][4][4];
    #pragma unroll
    for (int i = 0; i < 4; i++)
        #pragma unroll
        for (int j = 0; j < 4; j++)
            #pragma unroll
            for (int q = 0; q < 4; q++) acc[i][j][q] = 0.f;

    gemm_mainloop<DM, FH, true>(x, s_tok, nullptr, nullptr, 0,
                                W1 + (size_t)e * DM * FH, n0, smem_buf, acc);

    const int lane = tid & 31, wid = tid >> 5;
    const int wm = (wid >> 2) * 64, wn = (wid & 3) * 32;
    const float* b1e = b1 + (size_t)e * FH + n0;
    const int rem = cnt - row0;

    #pragma unroll
    for (int i = 0; i < 4; i++) {
        #pragma unroll
        for (int j = 0; j < 4; j++) {
            const int col = wn + j * 8 + 2 * (lane & 3);
            const float bb0 = b1e[col], bb1 = b1e[col + 1];
            #pragma unroll
            for (int h = 0; h < 2; h++) {
                const int r = wm + i * 16 + (lane >> 2) + h * 8;
                if (r < rem) {
                    const size_t slot = (size_t)off_e + row0 + r;
                    const float t0 = acc[i][j][2*h]   + bb0;
                    const float t1 = acc[i][j][2*h+1] + bb1;
                    const float q0 = 0.5f * t0 * (1.0f + erff(t0 * 0.70710678118654752440f));
                    const float q1 = 0.5f * t1 * (1.0f + erff(t1 * 0.70710678118654752440f));
                    __nv_bfloat16 h0 = __float2bfloat16(q0), h1 = __float2bfloat16(q1);
                    const float l0 = q0 - __bfloat162float(h0);
                    const float l1 = q1 - __bfloat162float(h1);
                    __nv_bfloat16 o0 = __float2bfloat16(l0), o1 = __float2bfloat16(l1);
                    const uint32_t vh = (uint32_t)__bfloat16_as_ushort(h0) |
                                        ((uint32_t)__bfloat16_as_ushort(h1) << 16);
                    const uint32_t vl = (uint32_t)__bfloat16_as_ushort(o0) |
                                        ((uint32_t)__bfloat16_as_ushort(o1) << 16);
                    *(uint32_t*)(g_hh + slot * FH + n0 + col) = vh;
                    *(uint32_t*)(g_hl + slot * FH + n0 + col) = vl;
                }
            }
        }
    }
}

// ---------------- GEMM2: y = hidden @ W2 + b2 -------------------------------
__global__ __launch_bounds__(256, 2)
void gemm2_kernel(const float* __restrict__ W2, const float* __restrict__ b2) {
    const int e = blockIdx.z;
    const int cnt = g_counts[e];
    const int row0 = blockIdx.y * 128;
    if (row0 >= cnt) return;
    const int n0 = blockIdx.x * 128;

    __shared__ __align__(128) char smem_buf[SMEM_TOTAL];
    const int tid = threadIdx.x;
    const int off_e = g_off[e];

    float acc[4][4][4];
    #pragma unroll
    for (int i = 0; i < 4; i++)
        #pragma unroll
        for (int j = 0; j < 4; j++)
            #pragma unroll
            for (int q = 0; q < 4; q++) acc[i][j][q] = 0.f;

    gemm_mainloop<FH, DM, false>(nullptr, nullptr, g_hh, g_hl,
                                 (size_t)(off_e + row0),
                                 W2 + (size_t)e * FH * DM, n0, smem_buf, acc);

    const int lane = tid & 31, wid = tid >> 5;
    const int wm = (wid >> 2) * 64, wn = (wid & 3) * 32;
    const float* b2e = b2 + (size_t)e * DM + n0;

    #pragma unroll
    for (int i = 0; i < 4; i++) {
        #pragma unroll
        for (int j = 0; j < 4; j++) {
            const int col = wn + j * 8 + 2 * (lane & 3);
            const float bb0 = b2e[col], bb1 = b2e[col + 1];
            #pragma unroll
            for (int h = 0; h < 2; h++) {
                const int r = wm + i * 16 + (lane >> 2) + h * 8;
                if (row0 + r < cnt) {
                    const int pair = g_pairs[e][row0 + r];
                    float2 v;
                    v.x = acc[i][j][2*h]   + bb0;
                    v.y = acc[i][j][2*h+1] + bb1;
                    *(float2*)(g_y + (size_t)pair * DM + n0 + col) = v;
                }
            }
        }
    }
}

// ---------------- combine ----------------------------------------------------
__global__ __launch_bounds__(256) void combine_kernel(float* __restrict__ out) {
    const int per_tok = DM / 4;
    const int i = blockIdx.x * blockDim.x + threadIdx.x;
    if (i >= T_TOK * per_tok) return;
    const int t = i / per_tok;
    const int c = i - t * per_tok;
    const float w0 = g_cw[2*t], w1 = g_cw[2*t + 1];
    const float4* y = (const float4*)g_y;
    const float4 a = y[(size_t)(2*t)     * per_tok + c];
    const float4 b = y[(size_t)(2*t + 1) * per_tok + c];
    float4 r;
    r.x = w0*a.x + w1*b.x;
    r.y = w0*a.y + w1*b.y;
    r.z = w0*a.z + w1*b.z;
    r.w = w0*a.w + w1*b.w;
    ((float4*)out)[i] = r;
}

// ---------------- launch ----------------------------------------------------
extern "C" void kernel_launch(void* const* d_in, const int* in_sizes, int n_in,
                              void* d_out, int out_size) {
    const float* x  = (const float*)d_in[0];
    const float* wg = (const float*)d_in[1];
    const float* W1 = (const float*)d_in[2];
    const float* b1 = (const float*)d_in[3];
    const float* W2 = (const float*)d_in[4];
    const float* b2 = (const float*)d_in[5];
    float* out = (float*)d_out;

    zero_counts_kernel<<<1, 32>>>();
    gate_kernel<<<T_TOK / 8, 256>>>(x, wg);
    prefix_kernel<<<1, 1>>>();
    gemm1_kernel<<<dim3(FH / 128, T_TOK / 128, NE), 256>>>(x, W1, b1);
    gemm2_kernel<<<dim3(DM / 128, T_TOK / 128, NE), 256>>>(W2, b2);
    combine_kernel<<<(T_TOK * (DM / 4) + 255) / 256, 256>>>(out);
}

// round 11
// speedup vs baseline: 3.7338x; 1.5000x over previous
#include <cuda_runtime.h>
#include <cuda_bf16.h>
#include <math.h>
#include <stdint.h>

#define T_TOK  8192
#define DM     1024
#define NE     8
#define FH     4096
#define NPAIR  (T_TOK*2)

// smem: 2 stages x 16KB. Stage: Ah[128m x 32B] Al Bh[16k x 256B] Bl (4KB each)
#define STAGE_B    16384
#define SMEM_TOTAL 32768

// ---------------- scratch (device globals; ~320MB total) --------------------
__device__ int   g_counts[NE];
__device__ int   g_off[NE];
__device__ int   g_pairs[NE][T_TOK];
__device__ float g_cw[NPAIR];
__device__ __align__(256) __nv_bfloat16 g_hh[(size_t)NPAIR * FH];  // hidden hi
__device__ __align__(256) __nv_bfloat16 g_hl[(size_t)NPAIR * FH];  // hidden lo
__device__ __align__(256) float g_y[(size_t)NPAIR * DM];

// ---------------- helpers ----------------------------------------------------
__device__ __forceinline__ uint32_t smem_u32(const void* p) {
    return (uint32_t)__cvta_generic_to_shared(p);
}
__device__ __forceinline__ void ldsm4(uint32_t* r, uint32_t addr) {
    asm volatile("ldmatrix.sync.aligned.m8n8.x4.shared.b16 {%0,%1,%2,%3}, [%4];"
                 : "=r"(r[0]), "=r"(r[1]), "=r"(r[2]), "=r"(r[3]) : "r"(addr));
}
__device__ __forceinline__ void ldsm4_t(uint32_t* r, uint32_t addr) {
    asm volatile("ldmatrix.sync.aligned.m8n8.x4.trans.shared.b16 {%0,%1,%2,%3}, [%4];"
                 : "=r"(r[0]), "=r"(r[1]), "=r"(r[2]), "=r"(r[3]) : "r"(addr));
}
__device__ __forceinline__ void mma_bf16(float* c, const uint32_t* a, const uint32_t* b) {
    asm volatile("mma.sync.aligned.m16n8k16.row.col.f32.bf16.bf16.f32 "
                 "{%0,%1,%2,%3}, {%4,%5,%6,%7}, {%8,%9}, {%0,%1,%2,%3};"
                 : "+f"(c[0]), "+f"(c[1]), "+f"(c[2]), "+f"(c[3])
                 : "r"(a[0]), "r"(a[1]), "r"(a[2]), "r"(a[3]), "r"(b[0]), "r"(b[1]));
}
// split 8 fp32 -> packed bf16 hi/lo (8 each)
__device__ __forceinline__ void split8(const float* v, uint4& h4, uint4& l4) {
    uint32_t h[4], l[4];
    #pragma unroll
    for (int j = 0; j < 4; j++) {
        __nv_bfloat16 h0 = __float2bfloat16(v[2*j]);
        __nv_bfloat16 h1 = __float2bfloat16(v[2*j+1]);
        float r0 = v[2*j]   - __bfloat162float(h0);
        float r1 = v[2*j+1] - __bfloat162float(h1);
        __nv_bfloat16 q0 = __float2bfloat16(r0), q1 = __float2bfloat16(r1);
        h[j] = (uint32_t)__bfloat16_as_ushort(h0) | ((uint32_t)__bfloat16_as_ushort(h1) << 16);
        l[j] = (uint32_t)__bfloat16_as_ushort(q0) | ((uint32_t)__bfloat16_as_ushort(q1) << 16);
    }
    h4 = make_uint4(h[0], h[1], h[2], h[3]);
    l4 = make_uint4(l[0], l[1], l[2], l[3]);
}

// ---------------- small kernels ---------------------------------------------
__global__ void zero_counts_kernel() {
    if (threadIdx.x < NE) g_counts[threadIdx.x] = 0;
}
__global__ void prefix_kernel() {
    if (threadIdx.x == 0) {
        int s = 0;
        for (int e = 0; e < NE; e++) { g_off[e] = s; s += g_counts[e]; }
    }
}

__global__ __launch_bounds__(256) void gate_kernel(const float* __restrict__ x,
                                                   const float* __restrict__ wg) {
    const int t = blockIdx.x * 8 + (threadIdx.x >> 5);
    const int lane = threadIdx.x & 31;
    if (t >= T_TOK) return;
    const float* xr = x + (size_t)t * DM;
    float acc[NE];
    #pragma unroll
    for (int e = 0; e < NE; e++) acc[e] = 0.f;
    for (int d = lane; d < DM; d += 32) {
        const float xv = xr[d];
        #pragma unroll
        for (int e = 0; e < NE; e++) acc[e] += xv * wg[e * DM + d];
    }
    #pragma unroll
    for (int e = 0; e < NE; e++)
        #pragma unroll
        for (int o = 16; o > 0; o >>= 1)
            acc[e] += __shfl_xor_sync(0xffffffffu, acc[e], o);
    if (lane == 0) {
        float m = acc[0];
        #pragma unroll
        for (int e = 1; e < NE; e++) m = fmaxf(m, acc[e]);
        float p[NE], s = 0.f;
        #pragma unroll
        for (int e = 0; e < NE; e++) { p[e] = expf(acc[e] - m); s += p[e]; }
        const float inv = 1.f / s;
        #pragma unroll
        for (int e = 0; e < NE; e++) p[e] *= inv;
        int e0 = 0;
        #pragma unroll
        for (int e = 1; e < NE; e++) if (p[e] > p[e0]) e0 = e;
        int e1 = -1;
        #pragma unroll
        for (int e = 0; e < NE; e++) {
            if (e == e0) continue;
            if (e1 < 0 || p[e] > p[e1]) e1 = e;
        }
        const int ee[2] = { e0, e1 };
        #pragma unroll
        for (int k = 0; k < 2; k++) {
            const int e = ee[k];
            const int idx = atomicAdd(&g_counts[e], 1);
            g_pairs[e][idx] = t * 2 + k;
            g_cw[t * 2 + k] = p[e];
        }
    }
}

// ---------------- unified mma mainloop ---------------------------------------
// CTA 128x128, 4 warps (2x2), warp tile 64x64, K chunks of 16.
// A smem: [m][k] 32B rows, XOR-swizzled 16B halves; ldmatrix (non-trans).
// B smem: [k][n] 256B rows, XOR-swizzled 16B chunks; ldmatrix.trans.
// Double buffer, one sync per chunk. Compensated bf16, term-major MMA order.
template<int KTOT, int BSTRIDE, bool SPLIT_A>
__device__ __forceinline__ void gemm_mainloop(
    const float* __restrict__ xsrc, const int* s_tok,         // SPLIT_A path
    const __nv_bfloat16* __restrict__ Ahg,
    const __nv_bfloat16* __restrict__ Alg, size_t a_row0,     // !SPLIT_A path
    const float* __restrict__ Bsrc, int n0,
    char* smem, float (&acc)[4][8][4])
{
    const int NCH = KTOT / 16;
    const int tid = threadIdx.x;   // 0..127
    const uint32_t sbase = smem_u32(smem);

    // loader mapping: A one row/thread (both halves); B chunks {bn, bn+8}
    const int am = tid;
    const int bk = tid >> 3, bn = tid & 7;
    const uint32_t aswz = (uint32_t)((am >> 2) & 1);
    const uint32_t aoff[2] = { (uint32_t)(am * 32) + ((0u ^ aswz) * 16u),
                               (uint32_t)(am * 32) + ((1u ^ aswz) * 16u) };
    const uint32_t boff[2] = { (uint32_t)(bk * 256 + (((bn    ) ^ (bk & 7)) * 16)),
                               (uint32_t)(bk * 256 + (((bn + 8) ^ (bk & 7)) * 16)) };

    const float* axp = nullptr;
    const __nv_bfloat16 *ahp = nullptr, *alp = nullptr;
    if constexpr (SPLIT_A) {
        axp = xsrc + (size_t)s_tok[am] * DM;
    } else {
        size_t r = a_row0 + am;
        if (r > (size_t)(NPAIR - 1)) r = NPAIR - 1;
        ahp = Ahg + r * KTOT;
        alp = Alg + r * KTOT;
    }
    const float* bb0 = Bsrc + (size_t)bk * BSTRIDE + n0 + bn * 8;
    const float* bb1 = bb0 + 64;

    // fragment geometry
    const int lane = tid & 31, wid = tid >> 5;
    const int wm = (wid >> 1) * 64, wn = (wid & 1) * 64;
    const int rA = wm + (lane & 15);
    const uint32_t offA = (uint32_t)(rA * 32) +
                          ((((lane >> 4) & 1) ^ ((rA >> 2) & 1)) ? 16u : 0u);
    const int bkr = lane & 15;                      // B ldsm k-row
    const int bnc0 = (wn >> 3) + ((lane >> 4) & 1); // B ldsm n-chunk base

    float ax[16]; uint4 ahv[2], alv[2]; float bx[16];

    #define LDG_CHUNK(c_) do {                                                   \
        const int kb = (c_) * 16;                                                \
        if constexpr (SPLIT_A) {                                                 \
            float4 t0 = *(const float4*)(axp + kb);                              \
            float4 t1 = *(const float4*)(axp + kb + 4);                          \
            float4 t2 = *(const float4*)(axp + kb + 8);                          \
            float4 t3 = *(const float4*)(axp + kb + 12);                         \
            ax[0]=t0.x; ax[1]=t0.y; ax[2]=t0.z; ax[3]=t0.w;                      \
            ax[4]=t1.x; ax[5]=t1.y; ax[6]=t1.z; ax[7]=t1.w;                      \
            ax[8]=t2.x; ax[9]=t2.y; ax[10]=t2.z; ax[11]=t2.w;                    \
            ax[12]=t3.x; ax[13]=t3.y; ax[14]=t3.z; ax[15]=t3.w;                  \
        } else {                                                                 \
            ahv[0] = *(const uint4*)(ahp + kb);                                  \
            ahv[1] = *(const uint4*)(ahp + kb + 8);                              \
            alv[0] = *(const uint4*)(alp + kb);                                  \
            alv[1] = *(const uint4*)(alp + kb + 8);                              \
        }                                                                        \
        const float* bp0 = bb0 + (size_t)kb * BSTRIDE;                           \
        const float* bp1 = bb1 + (size_t)kb * BSTRIDE;                           \
        float4 u0 = *(const float4*)(bp0);                                       \
        float4 u1 = *(const float4*)(bp0 + 4);                                   \
        float4 u2 = *(const float4*)(bp1);                                       \
        float4 u3 = *(const float4*)(bp1 + 4);                                   \
        bx[0]=u0.x; bx[1]=u0.y; bx[2]=u0.z; bx[3]=u0.w;                          \
        bx[4]=u1.x; bx[5]=u1.y; bx[6]=u1.z; bx[7]=u1.w;                          \
        bx[8]=u2.x; bx[9]=u2.y; bx[10]=u2.z; bx[11]=u2.w;                        \
        bx[12]=u3.x; bx[13]=u3.y; bx[14]=u3.z; bx[15]=u3.w;                      \
    } while (0)

    #define STS_CHUNK(s_) do {                                                   \
        char* st = smem + (s_) * STAGE_B;                                        \
        _Pragma("unroll")                                                        \
        for (int g = 0; g < 2; g++) {                                            \
            if constexpr (SPLIT_A) {                                             \
                uint4 h4, l4; split8(ax + g * 8, h4, l4);                        \
                *(uint4*)(st + aoff[g])        = h4;                             \
                *(uint4*)(st + 4096 + aoff[g]) = l4;                             \
            } else {                                                             \
                *(uint4*)(st + aoff[g])        = ahv[g];                         \
                *(uint4*)(st + 4096 + aoff[g]) = alv[g];                         \
            }                                                                    \
            uint4 bh4, bl4; split8(bx + g * 8, bh4, bl4);                        \
            *(uint4*)(st + 8192  + boff[g]) = bh4;                               \
            *(uint4*)(st + 12288 + boff[g]) = bl4;                               \
        }                                                                        \
    } while (0)

    LDG_CHUNK(0);
    for (int c = 0; c < NCH; c++) {
        const int s = c & 1;
        STS_CHUNK(s);
        if (c + 1 < NCH) LDG_CHUNK(c + 1);
        __syncthreads();            // stage s stores visible; c-2 reads done
        const uint32_t so = sbase + (uint32_t)s * STAGE_B;

        uint32_t ah[4][4], al[4][4], bh[4][4], bl[4][4];
        #pragma unroll
        for (int i = 0; i < 4; i++) {
            ldsm4(ah[i], so + offA + (uint32_t)(i * 16 * 32));
            ldsm4(al[i], so + 4096u + offA + (uint32_t)(i * 16 * 32));
        }
        #pragma unroll
        for (int jp = 0; jp < 4; jp++) {
            const uint32_t bo = (uint32_t)(bkr * 256 +
                                (((bnc0 + jp * 2) ^ (bkr & 7)) * 16));
            ldsm4_t(bh[jp], so + 8192u  + bo);
            ldsm4_t(bl[jp], so + 12288u + bo);
        }
        // term-major: three passes of 32 independent MMAs each
        #pragma unroll
        for (int i = 0; i < 4; i++)
            #pragma unroll
            for (int j = 0; j < 8; j++)
                mma_bf16(acc[i][j], ah[i], &bh[j >> 1][(j & 1) * 2]);
        #pragma unroll
        for (int i = 0; i < 4; i++)
            #pragma unroll
            for (int j = 0; j < 8; j++)
                mma_bf16(acc[i][j], ah[i], &bl[j >> 1][(j & 1) * 2]);
        #pragma unroll
        for (int i = 0; i < 4; i++)
            #pragma unroll
            for (int j = 0; j < 8; j++)
                mma_bf16(acc[i][j], al[i], &bh[j >> 1][(j & 1) * 2]);
    }
    #undef LDG_CHUNK
    #undef STS_CHUNK
}

// ---------------- GEMM1: hidden = gelu(x @ W1 + b1) -> bf16 hi/lo -----------
__global__ __launch_bounds__(128, 2)
void gemm1_kernel(const float* __restrict__ x, const float* __restrict__ W1,
                  const float* __restrict__ b1) {
    const int e = blockIdx.z;
    const int cnt = g_counts[e];
    const int row0 = blockIdx.y * 128;
    if (row0 >= cnt) return;
    const int n0 = blockIdx.x * 128;

    __shared__ __align__(128) char smem_buf[SMEM_TOTAL];
    __shared__ int s_tok[128];
    const int tid = threadIdx.x;
    {
        const int slot = row0 + tid;
        s_tok[tid] = (slot < cnt) ? (g_pairs[e][slot] >> 1) : 0;
    }
    __syncthreads();
    const int off_e = g_off[e];

    float acc[4][8][4];
    #pragma unroll
    for (int i = 0; i < 4; i++)
        #pragma unroll
        for (int j = 0; j < 8; j++)
            #pragma unroll
            for (int q = 0; q < 4; q++) acc[i][j][q] = 0.f;

    gemm_mainloop<DM, FH, true>(x, s_tok, nullptr, nullptr, 0,
                                W1 + (size_t)e * DM * FH, n0, smem_buf, acc);

    const int lane = tid & 31, wid = tid >> 5;
    const int wm = (wid >> 1) * 64, wn = (wid & 1) * 64;
    const float* b1e = b1 + (size_t)e * FH + n0;
    const int rem = cnt - row0;

    #pragma unroll
    for (int i = 0; i < 4; i++) {
        #pragma unroll
        for (int j = 0; j < 8; j++) {
            const int col = wn + j * 8 + 2 * (lane & 3);
            const float bb0 = b1e[col], bb1 = b1e[col + 1];
            #pragma unroll
            for (int h = 0; h < 2; h++) {
                const int r = wm + i * 16 + (lane >> 2) + h * 8;
                if (r < rem) {
                    const size_t slot = (size_t)off_e + row0 + r;
                    const float t0 = acc[i][j][2*h]   + bb0;
                    const float t1 = acc[i][j][2*h+1] + bb1;
                    const float q0 = 0.5f * t0 * (1.0f + erff(t0 * 0.70710678118654752440f));
                    const float q1 = 0.5f * t1 * (1.0f + erff(t1 * 0.70710678118654752440f));
                    __nv_bfloat16 h0 = __float2bfloat16(q0), h1 = __float2bfloat16(q1);
                    const float l0 = q0 - __bfloat162float(h0);
                    const float l1 = q1 - __bfloat162float(h1);
                    __nv_bfloat16 o0 = __float2bfloat16(l0), o1 = __float2bfloat16(l1);
                    const uint32_t vh = (uint32_t)__bfloat16_as_ushort(h0) |
                                        ((uint32_t)__bfloat16_as_ushort(h1) << 16);
                    const uint32_t vl = (uint32_t)__bfloat16_as_ushort(o0) |
                                        ((uint32_t)__bfloat16_as_ushort(o1) << 16);
                    *(uint32_t*)(g_hh + slot * FH + n0 + col) = vh;
                    *(uint32_t*)(g_hl + slot * FH + n0 + col) = vl;
                }
            }
        }
    }
}

// ---------------- GEMM2: y = hidden @ W2 + b2 -------------------------------
__global__ __launch_bounds__(128, 2)
void gemm2_kernel(const float* __restrict__ W2, const float* __restrict__ b2) {
    const int e = blockIdx.z;
    const int cnt = g_counts[e];
    const int row0 = blockIdx.y * 128;
    if (row0 >= cnt) return;
    const int n0 = blockIdx.x * 128;

    __shared__ __align__(128) char smem_buf[SMEM_TOTAL];
    const int tid = threadIdx.x;
    const int off_e = g_off[e];

    float acc[4][8][4];
    #pragma unroll
    for (int i = 0; i < 4; i++)
        #pragma unroll
        for (int j = 0; j < 8; j++)
            #pragma unroll
            for (int q = 0; q < 4; q++) acc[i][j][q] = 0.f;

    gemm_mainloop<FH, DM, false>(nullptr, nullptr, g_hh, g_hl,
                                 (size_t)(off_e + row0),
                                 W2 + (size_t)e * FH * DM, n0, smem_buf, acc);

    const int lane = tid & 31, wid = tid >> 5;
    const int wm = (wid >> 1) * 64, wn = (wid & 1) * 64;
    const float* b2e = b2 + (size_t)e * DM + n0;

    #pragma unroll
    for (int i = 0; i < 4; i++) {
        #pragma unroll
        for (int j = 0; j < 8; j++) {
            const int col = wn + j * 8 + 2 * (lane & 3);
            const float bb0 = b2e[col], bb1 = b2e[col + 1];
            #pragma unroll
            for (int h = 0; h < 2; h++) {
                const int r = wm + i * 16 + (lane >> 2) + h * 8;
                if (row0 + r < cnt) {
                    const int pair = g_pairs[e][row0 + r];
                    float2 v;
                    v.x = acc[i][j][2*h]   + bb0;
                    v.y = acc[i][j][2*h+1] + bb1;
                    *(float2*)(g_y + (size_t)pair * DM + n0 + col) = v;
                }
            }
        }
    }
}

// ---------------- combine ----------------------------------------------------
__global__ __launch_bounds__(256) void combine_kernel(float* __restrict__ out) {
    const int per_tok = DM / 4;
    const int i = blockIdx.x * blockDim.x + threadIdx.x;
    if (i >= T_TOK * per_tok) return;
    const int t = i / per_tok;
    const int c = i - t * per_tok;
    const float w0 = g_cw[2*t], w1 = g_cw[2*t + 1];
    const float4* y = (const float4*)g_y;
    const float4 a = y[(size_t)(2*t)     * per_tok + c];
    const float4 b = y[(size_t)(2*t + 1) * per_tok + c];
    float4 r;
    r.x = w0*a.x + w1*b.x;
    r.y = w0*a.y + w1*b.y;
    r.z = w0*a.z + w1*b.z;
    r.w = w0*a.w + w1*b.w;
    ((float4*)out)[i] = r;
}

// ---------------- launch ----------------------------------------------------
extern "C" void kernel_launch(void* const* d_in, const int* in_sizes, int n_in,
                              void* d_out, int out_size) {
    const float* x  = (const float*)d_in[0];
    const float* wg = (const float*)d_in[1];
    const float* W1 = (const float*)d_in[2];
    const float* b1 = (const float*)d_in[3];
    const float* W2 = (const float*)d_in[4];
    const float* b2 = (const float*)d_in[5];
    float* out = (float*)d_out;

    zero_counts_kernel<<<1, 32>>>();
    gate_kernel<<<T_TOK / 8, 256>>>(x, wg);
    prefix_kernel<<<1, 1>>>();
    gemm1_kernel<<<dim3(FH / 128, T_TOK / 128, NE), 128>>>(x, W1, b1);
    gemm2_kernel<<<dim3(DM / 128, T_TOK / 128, NE), 128>>>(W2, b2);
    combine_kernel<<<(T_TOK * (DM / 4) + 255) / 256, 256>>>(out);
}